// round 6
// baseline (speedup 1.0000x reference)
#include <cuda_runtime.h>

// SegGPS_66949950210076
// out[b] = sum_m prod_l eps[idx[b,l], m, l, nup[b,l], ndn[b,l]]
// B=8192, L=64, M=64, LOCAL_DIM=4, eps (4,64,64,65,65) fp32.
//
// R5: 4 lean kernels, no bulk clears.
//  detect  : dtype probe (g_is_int32 zero-init, set-only -> no reset kernel)
//  flag    : mark touched (l,nup,ndn,idx) cells (byte flags)
//  transpose: warp-ballot per row (l,nup,idx); per flagged cell 32 lanes move
//             64 m-strided floats into T[cell][idx][m] (256B contiguous)
//  seggps  : warp per batch, float2 per lane, gathers 256B/site from
//            L2-resident T; clears its own flags at the end (invariant:
//            flags all-zero at every launch entry).

#define B_SZ   8192
#define L_SZ   64
#define IDX_STRIDE 17305600   // M*L*65*65
#define M_STRIDE   270400     // L*65*65
#define L_STRIDE   4225       // 65*65
#define CELLS  89440          // sum_{k=1..64} k^2
#define T_ELEMS (CELLS * 256)

__device__ float         g_T[T_ELEMS];        // 91.6 MB scratch (static)
__device__ unsigned char g_flags[4][CELLS];   // zero-init; self-cleaned
__device__ int           g_is_int32;          // zero-init; set-only

__device__ __forceinline__ int cell_off(int l) {
    return l * (l + 1) * (2 * l + 1) / 6;     // sum_{j=1..l} j^2
}

// Indices are logically int64 (ref) but JAX x64-off emits int32. Under int64
// LE every odd 32-bit word is 0 (values < 4); under int32 odd words are
// random in [0,4) -> P(all 2048 zero) = 0.25^2048. Words scanned (< 4096)
// are in-bounds under either layout (>= 524288 words exist).
__global__ void detect_kernel(const unsigned* __restrict__ w) {
    int i = blockIdx.x * blockDim.x + threadIdx.x;   // 0..2047
    if (w[2 * i + 1] != 0u) g_is_int32 = 1;
}

// Per-warp scan of one batch: two ballots cover all 64 sites.
__device__ __forceinline__ void scan_batch(
    const void* idx_raw, int b, int lane,
    int& v0, int& v1, int& cell0, int& cell1)
{
    if (g_is_int32) {
        const int* p = (const int*)idx_raw + b * L_SZ;
        v0 = p[lane];  v1 = p[lane + 32];
    } else {
        const long long* p = (const long long*)idx_raw + (size_t)b * L_SZ;
        v0 = (int)p[lane];  v1 = (int)p[lane + 32];
    }
    unsigned bu0 = __ballot_sync(0xffffffffu, v0 & 1);
    unsigned bd0 = __ballot_sync(0xffffffffu, v0 & 2);
    unsigned bu1 = __ballot_sync(0xffffffffu, v1 & 1);
    unsigned bd1 = __ballot_sync(0xffffffffu, v1 & 2);
    unsigned mlt = (1u << lane) - 1u;
    int nup0 = __popc(bu0 & mlt),               ndn0 = __popc(bd0 & mlt);
    int nup1 = __popc(bu0) + __popc(bu1 & mlt), ndn1 = __popc(bd0) + __popc(bd1 & mlt);
    cell0 = cell_off(lane)      + nup0 * (lane + 1)  + ndn0;
    cell1 = cell_off(lane + 32) + nup1 * (lane + 33) + ndn1;
}

// ---- mark touched cells ----
__global__ __launch_bounds__(256) void flag_kernel(const void* __restrict__ idx_raw) {
    int lane = threadIdx.x & 31;
    int b = blockIdx.x * 8 + (threadIdx.x >> 5);
    int v0, v1, c0, c1;
    scan_batch(idx_raw, b, lane, v0, v1, c0, c1);
    g_flags[v0][c0] = 1;
    g_flags[v1][c1] = 1;
}

// ---- transpose: 64-thread CTA per (l, nup, idx) row; warp-ballot cells ----
__global__ __launch_bounds__(64) void transpose_kernel(const float* __restrict__ eps) {
    const int l = blockIdx.x, nup = blockIdx.y, idx = blockIdx.z;
    if (nup > l) return;
    const int nv = l + 1;

    const int lane = threadIdx.x & 31;
    const int ndn0 = (threadIdx.x >> 5) * 32;        // warp0: ndn 0..31, warp1: 32..63
    const int cellbase = cell_off(l) + nup * nv;

    const int c = ndn0 + lane;
    int f = (c < nv) ? g_flags[idx][cellbase + c] : 0;
    unsigned ball = __ballot_sync(0xffffffffu, f);

    const float* src = eps + idx * IDX_STRIDE + l * L_STRIDE + nup * 65;
    while (ball) {
        int bit = __ffs(ball) - 1;  ball &= ball - 1;
        int ndn = ndn0 + bit;
        float a = __ldg(src + ndn + lane * M_STRIDE);          // m = lane
        float b = __ldg(src + ndn + (lane + 32) * M_STRIDE);   // m = lane+32
        float* dst = g_T + (cellbase + ndn) * 256 + idx * 64;
        dst[lane]      = a;                                    // 256B coalesced
        dst[lane + 32] = b;
    }
}

// ---- gather: warp per batch, float2 per lane; clears own flags ----
__global__ __launch_bounds__(512) void seggps_kernel(
    const void* __restrict__ idx_raw,
    float*      __restrict__ out)
{
    __shared__ int soffs[16][64];

    const int lane = threadIdx.x & 31;
    const int w    = threadIdx.x >> 5;
    const int b    = blockIdx.x * 16 + w;

    int v0, v1, c0, c1;
    scan_batch(idx_raw, b, lane, v0, v1, c0, c1);
    soffs[w][lane]      = c0 * 256 + v0 * 64;
    soffs[w][lane + 32] = c1 * 256 + v1 * 64;

    // restore the all-zero flag invariant for the next launch
    g_flags[v0][c0] = 0;
    g_flags[v1][c1] = 0;
    __syncwarp();

    float p0x = 1.f, p0y = 1.f, p1x = 1.f, p1y = 1.f;
    float p2x = 1.f, p2y = 1.f, p3x = 1.f, p3y = 1.f;
    #pragma unroll
    for (int l = 0; l < L_SZ; l += 4) {
        float2 a  = __ldg((const float2*)(g_T + soffs[w][l + 0]) + lane);
        float2 b2 = __ldg((const float2*)(g_T + soffs[w][l + 1]) + lane);
        float2 c  = __ldg((const float2*)(g_T + soffs[w][l + 2]) + lane);
        float2 d  = __ldg((const float2*)(g_T + soffs[w][l + 3]) + lane);
        p0x *= a.x;  p0y *= a.y;
        p1x *= b2.x; p1y *= b2.y;
        p2x *= c.x;  p2y *= c.y;
        p3x *= d.x;  p3y *= d.y;
    }
    float s = (p0x * p1x) * (p2x * p3x) + (p0y * p1y) * (p2y * p3y);

    #pragma unroll
    for (int o = 16; o; o >>= 1) s += __shfl_xor_sync(0xffffffffu, s, o);
    if (lane == 0) out[b] = s;
}

extern "C" void kernel_launch(void* const* d_in, const int* in_sizes, int n_in,
                              void* d_out, int out_size)
{
    const void*  idx = d_in[0];                 // indices (B,L) int32 or int64
    const float* eps = (const float*)d_in[1];   // epsilon fp32
    float* out = (float*)d_out;
    (void)in_sizes; (void)n_in; (void)out_size;

    detect_kernel<<<8, 256>>>((const unsigned*)idx);
    flag_kernel<<<B_SZ / 8, 256>>>(idx);
    transpose_kernel<<<dim3(64, 64, 4), 64>>>(eps);
    seggps_kernel<<<B_SZ / 16, 512>>>(idx, out);
}

// round 8
// speedup vs baseline: 1.3043x; 1.3043x over previous
#include <cuda_runtime.h>

// SegGPS_66949950210076
// out[b] = sum_m prod_l eps[idx[b,l], m, l, nup[b,l], ndn[b,l]]
// B=8192, L=64, M=64, LOCAL_DIM=4, eps (4,64,64,65,65) fp32.
//
// R6: detect -> flag -> transpose(idx-loop, smem, self-clearing flags)
//     -> gather (float4 lane-split, store-free).
// T[cell][idx][m] (m contiguous 256B) holds only batch-touched cells; L2-res.

#define B_SZ   8192
#define L_SZ   64
#define IDX_STRIDE 17305600   // M*L*65*65
#define M_STRIDE   270400     // L*65*65
#define L_STRIDE   4225       // 65*65
#define CELLS  89440          // sum_{k=1..64} k^2
#define T_ELEMS (CELLS * 256)

__device__ __align__(256) float g_T[T_ELEMS]; // 91.6 MB scratch (static)
__device__ unsigned char g_flags[4][CELLS];   // zero-init; transpose self-clears
__device__ int           g_is_int32;          // zero-init; set-only

__device__ __forceinline__ int cell_off(int l) {
    return l * (l + 1) * (2 * l + 1) / 6;     // sum_{j=1..l} j^2
}
__device__ __forceinline__ float4 mul4(float4 a, float4 b) {
    return make_float4(a.x * b.x, a.y * b.y, a.z * b.z, a.w * b.w);
}

// Indices are logically int64 (ref) but JAX x64-off emits int32. Under int64
// LE every odd 32-bit word is 0 (values < 4); under int32 odd words are random
// in [0,4): P(all 2048 zero) = 0.25^2048. Scanned words (<4096) are in-bounds
// under either layout. g_is_int32 is set-only -> no reset kernel needed.
__global__ void detect_kernel(const unsigned* __restrict__ w) {
    int i = blockIdx.x * blockDim.x + threadIdx.x;   // 0..2047
    if (w[2 * i + 1] != 0u) g_is_int32 = 1;
}

// Per-warp scan of one batch: two ballots cover all 64 sites.
__device__ __forceinline__ void scan_batch(
    const void* idx_raw, int b, int lane,
    int& v0, int& v1, int& cell0, int& cell1)
{
    if (g_is_int32) {
        const int* p = (const int*)idx_raw + b * L_SZ;
        v0 = p[lane];  v1 = p[lane + 32];
    } else {
        const long long* p = (const long long*)idx_raw + (size_t)b * L_SZ;
        v0 = (int)p[lane];  v1 = (int)p[lane + 32];
    }
    unsigned bu0 = __ballot_sync(0xffffffffu, v0 & 1);
    unsigned bd0 = __ballot_sync(0xffffffffu, v0 & 2);
    unsigned bu1 = __ballot_sync(0xffffffffu, v1 & 1);
    unsigned bd1 = __ballot_sync(0xffffffffu, v1 & 2);
    unsigned mlt = (1u << lane) - 1u;
    int nup0 = __popc(bu0 & mlt),               ndn0 = __popc(bd0 & mlt);
    int nup1 = __popc(bu0) + __popc(bu1 & mlt), ndn1 = __popc(bd0) + __popc(bd1 & mlt);
    cell0 = cell_off(lane)      + nup0 * (lane + 1)  + ndn0;
    cell1 = cell_off(lane + 32) + nup1 * (lane + 33) + ndn1;
}

// ---- mark touched cells ----
__global__ __launch_bounds__(256) void flag_kernel(const void* __restrict__ idx_raw) {
    int lane = threadIdx.x & 31;
    int b = blockIdx.x * 8 + (threadIdx.x >> 5);
    int v0, v1, c0, c1;
    scan_batch(idx_raw, b, lane, v0, v1, c0, c1);
    g_flags[v0][c0] = 1;
    g_flags[v1][c1] = 1;
}

// ---- transpose: CTA per (l, nup), loops idx 0..3; self-clears flags ----
__global__ __launch_bounds__(256) void transpose_kernel(const float* __restrict__ eps) {
    const int l = blockIdx.x, nup = blockIdx.y;
    if (nup > l) return;
    const int nv = l + 1;
    const int cellbase = cell_off(l) + nup * nv;

    __shared__ float         sm[64][65];
    __shared__ unsigned char sflag[4][64];
    __shared__ unsigned      sball[8];

    const int tid  = threadIdx.x;
    const int lane = tid & 31;
    const int wf   = tid >> 5;              // 8 warps: (idx_f, ndn-half)
    const int idxf = wf >> 1;
    const int c32  = (wf & 1) * 32 + lane;

    // prefetch all 4 idx flag-rows, record per-warp any-ballot, clear flags
    int f = (c32 < nv) ? g_flags[idxf][cellbase + c32] : 0;
    unsigned ball = __ballot_sync(0xffffffffu, f);
    if (lane == 0) sball[wf] = ball;
    sflag[idxf][c32] = (unsigned char)f;
    if (f) g_flags[idxf][cellbase + c32] = 0;   // restore all-zero invariant
    __syncthreads();

    const int c  = tid & 63;        // read phase: ndn ; write phase: m
    const int r4 = tid >> 6;

    for (int idx = 0; idx < 4; idx++) {
        if (!(sball[2 * idx] | sball[2 * idx + 1])) continue;

        const float* src = eps + idx * IDX_STRIDE + l * L_STRIDE + nup * 65;
        if (c < nv && sflag[idx][c]) {
            #pragma unroll
            for (int mb = 0; mb < 64; mb += 4) {
                int m = mb + r4;
                sm[m][c] = src[m * M_STRIDE + c];   // coalesced along ndn
            }
        }
        __syncthreads();

        float* dst = g_T + cellbase * 256 + idx * 64;
        #pragma unroll
        for (int nb = 0; nb < 64; nb += 4) {
            int ndn = nb + r4;
            if (ndn < nv && sflag[idx][ndn])
                dst[ndn * 256 + c] = sm[c][ndn];    // 256B coalesced
        }
        __syncthreads();
    }
}

// ---- gather: warp per batch; float4, lane-split (even/odd sites) ----
__global__ __launch_bounds__(256) void seggps_kernel(
    const void* __restrict__ idx_raw,
    float*      __restrict__ out)
{
    __shared__ int soffs[8][64];

    const int lane = threadIdx.x & 31;
    const int w    = threadIdx.x >> 5;
    const int b    = blockIdx.x * 8 + w;

    int v0, v1, c0, c1;
    scan_batch(idx_raw, b, lane, v0, v1, c0, c1);
    soffs[w][lane]      = c0 * 256 + v0 * 64;
    soffs[w][lane + 32] = c1 * 256 + v1 * 64;
    __syncwarp();

    // lanes 0-15: even sites; lanes 16-31: odd sites. q = m-quad (4 floats).
    const int half = lane >> 4;
    const int q    = lane & 15;

    float4 a0 = make_float4(1.f, 1.f, 1.f, 1.f), a1 = a0, a2 = a0, a3 = a0;
    #pragma unroll
    for (int i = 0; i < 32; i += 4) {
        float4 x0 = __ldg((const float4*)(g_T + soffs[w][2 * (i + 0) + half]) + q);
        float4 x1 = __ldg((const float4*)(g_T + soffs[w][2 * (i + 1) + half]) + q);
        float4 x2 = __ldg((const float4*)(g_T + soffs[w][2 * (i + 2) + half]) + q);
        float4 x3 = __ldg((const float4*)(g_T + soffs[w][2 * (i + 3) + half]) + q);
        a0 = mul4(a0, x0);
        a1 = mul4(a1, x1);
        a2 = mul4(a2, x2);
        a3 = mul4(a3, x3);
    }
    float4 p = mul4(mul4(a0, a1), mul4(a2, a3));   // this half's product

    // combine halves: lane j and j+16 both end with full product of quad j
    float4 o;
    o.x = __shfl_xor_sync(0xffffffffu, p.x, 16);
    o.y = __shfl_xor_sync(0xffffffffu, p.y, 16);
    o.z = __shfl_xor_sync(0xffffffffu, p.z, 16);
    o.w = __shfl_xor_sync(0xffffffffu, p.w, 16);
    p = mul4(p, o);

    float s = (p.x + p.y) + (p.z + p.w);           // sum over quad's 4 m
    #pragma unroll
    for (int off = 8; off; off >>= 1) s += __shfl_xor_sync(0xffffffffu, s, off);
    if (lane == 0) out[b] = s;                     // sum over quads 0..15
}

extern "C" void kernel_launch(void* const* d_in, const int* in_sizes, int n_in,
                              void* d_out, int out_size)
{
    const void*  idx = d_in[0];                 // indices (B,L) int32 or int64
    const float* eps = (const float*)d_in[1];   // epsilon fp32
    float* out = (float*)d_out;
    (void)in_sizes; (void)n_in; (void)out_size;

    detect_kernel<<<8, 256>>>((const unsigned*)idx);
    flag_kernel<<<B_SZ / 8, 256>>>(idx);
    transpose_kernel<<<dim3(64, 64), 256>>>(eps);
    seggps_kernel<<<B_SZ / 8, 256>>>(idx, out);
}